// round 8
// baseline (speedup 1.0000x reference)
#include <cuda_runtime.h>
#include <cstdint>

// LIF scan: x (N=32, T=16, C=128, H=32, W=32) f32 -> spikes same shape.
// v = v*0.5 + x_t; spike = (v >= 1); v -= spike.  v_init structurally zero.
//
// At the LTS ceiling (6.87 TB/s effective with LDG.256). This round:
//  - software pipelining: next batch's 4x LDG.256 issue BEFORE current
//    batch's stores, so reads stay outstanding across batch boundaries
//  - persistent grid-stride (148 SMs x 4 CTAs) to remove wave transitions

#define N_BATCH 32
#define T_STEPS 16
#define S_ELEMS (128 * 32 * 32)      // 131072 elements per (n,t) plane
#define SV8 (S_ELEMS / 8)            // 16384 8-float groups per plane
#define TOTAL_GROUPS (N_BATCH * SV8) // 524288 work items

struct f8 { float v[8]; };

__device__ __forceinline__ f8 ldg256(const float* p) {
    f8 r;
    asm volatile("ld.global.v8.b32 {%0,%1,%2,%3,%4,%5,%6,%7}, [%8];"
                 : "=f"(r.v[0]), "=f"(r.v[1]), "=f"(r.v[2]), "=f"(r.v[3]),
                   "=f"(r.v[4]), "=f"(r.v[5]), "=f"(r.v[6]), "=f"(r.v[7])
                 : "l"(p));
    return r;
}

__device__ __forceinline__ void stg256(float* p, const f8& r) {
    asm volatile("st.global.v8.b32 [%0], {%1,%2,%3,%4,%5,%6,%7,%8};"
                 :: "l"(p),
                    "f"(r.v[0]), "f"(r.v[1]), "f"(r.v[2]), "f"(r.v[3]),
                    "f"(r.v[4]), "f"(r.v[5]), "f"(r.v[6]), "f"(r.v[7])
                 : "memory");
}

__device__ __forceinline__ void lif_step8(float* __restrict__ v, f8& x) {
#pragma unroll
    for (int i = 0; i < 8; ++i) {
        float vi = v[i] * 0.5f + x.v[i];
        float sp = (vi >= 1.0f) ? 1.0f : 0.0f;
        v[i] = vi - sp;
        x.v[i] = sp;                 // spike overwrites the input slot
    }
}

__global__ __launch_bounds__(256) void lif_kernel(
    const float* __restrict__ x,
    float* __restrict__ out)
{
    const int nthreads = gridDim.x * blockDim.x;

    for (int tid = blockIdx.x * blockDim.x + threadIdx.x;
         tid < TOTAL_GROUPS; tid += nthreads)
    {
        const int n = tid >> 14;           // tid / SV8
        const int g = tid & (SV8 - 1);     // tid % SV8

        const float* xp = x   + ((size_t)n * T_STEPS * SV8 + g) * 8;
        float*       op = out + ((size_t)n * T_STEPS * SV8 + g) * 8;
        const size_t stride = (size_t)SV8 * 8;   // one timestep plane, floats

        float v[8];
#pragma unroll
        for (int i = 0; i < 8; ++i) v[i] = 0.0f;   // v_init == 0

        // ---- software-pipelined: batch A loads, then per-batch:
        //      load(next) -> compute(cur) -> store(cur) ----
        f8 a0 = ldg256(xp + 0 * stride);
        f8 a1 = ldg256(xp + 1 * stride);
        f8 a2 = ldg256(xp + 2 * stride);
        f8 a3 = ldg256(xp + 3 * stride);

#pragma unroll
        for (int tb = 0; tb < T_STEPS - 4; tb += 4) {
            // prefetch next batch while current batch's loads complete
            f8 b0 = ldg256(xp + (size_t)(tb + 4) * stride);
            f8 b1 = ldg256(xp + (size_t)(tb + 5) * stride);
            f8 b2 = ldg256(xp + (size_t)(tb + 6) * stride);
            f8 b3 = ldg256(xp + (size_t)(tb + 7) * stride);

            lif_step8(v, a0);
            lif_step8(v, a1);
            lif_step8(v, a2);
            lif_step8(v, a3);

            stg256(op + (size_t)(tb + 0) * stride, a0);
            stg256(op + (size_t)(tb + 1) * stride, a1);
            stg256(op + (size_t)(tb + 2) * stride, a2);
            stg256(op + (size_t)(tb + 3) * stride, a3);

            a0 = b0; a1 = b1; a2 = b2; a3 = b3;
        }

        // epilogue: last batch
        lif_step8(v, a0);
        lif_step8(v, a1);
        lif_step8(v, a2);
        lif_step8(v, a3);
        stg256(op + (size_t)(T_STEPS - 4) * stride, a0);
        stg256(op + (size_t)(T_STEPS - 3) * stride, a1);
        stg256(op + (size_t)(T_STEPS - 2) * stride, a2);
        stg256(op + (size_t)(T_STEPS - 1) * stride, a3);
    }
}

extern "C" void kernel_launch(void* const* d_in, const int* in_sizes, int n_in,
                              void* d_out, int out_size)
{
    const float* x   = (const float*)d_in[0];
    float*       out = (float*)d_out;

    const int block = 256;
    const int grid  = 148 * 4;   // persistent: 4 CTAs per SM, grid-stride

    lif_kernel<<<grid, block>>>(x, out);
}

// round 9
// speedup vs baseline: 1.0303x; 1.0303x over previous
#include <cuda_runtime.h>
#include <cstdint>

// LIF scan: x (N=32, T=16, C=128, H=32, W=32) f32 -> spikes same shape.
// v = v*0.5 + x_t; spike = (v >= 1); v -= spike.  v_init structurally zero.
//
// CONVERGED configuration (best of 6 measured variants, R7): 256-bit global
// accesses (LDG.256/STG.256), 4-deep load batching (MLP=4/thread), regs=58,
// occ=43%. 6.87 TB/s effective = ~97% of the LTS chip ceiling (~6300 B/cyc).
// Both deeper pipelining (regs 96, occ 23% -> 77.3us) and shallower/hinted
// variants measured slower. Traffic (512 MB) is irreducible; compute ~4%.

#define N_BATCH 32
#define T_STEPS 16
#define S_ELEMS (128 * 32 * 32)      // 131072 elements per (n,t) plane
#define SV8 (S_ELEMS / 8)            // 16384 8-float groups per plane

struct f8 { float v[8]; };

__device__ __forceinline__ f8 ldg256(const float* p) {
    f8 r;
    asm volatile("ld.global.v8.b32 {%0,%1,%2,%3,%4,%5,%6,%7}, [%8];"
                 : "=f"(r.v[0]), "=f"(r.v[1]), "=f"(r.v[2]), "=f"(r.v[3]),
                   "=f"(r.v[4]), "=f"(r.v[5]), "=f"(r.v[6]), "=f"(r.v[7])
                 : "l"(p));
    return r;
}

__device__ __forceinline__ void stg256(float* p, const f8& r) {
    asm volatile("st.global.v8.b32 [%0], {%1,%2,%3,%4,%5,%6,%7,%8};"
                 :: "l"(p),
                    "f"(r.v[0]), "f"(r.v[1]), "f"(r.v[2]), "f"(r.v[3]),
                    "f"(r.v[4]), "f"(r.v[5]), "f"(r.v[6]), "f"(r.v[7])
                 : "memory");
}

__device__ __forceinline__ void lif_step8(float* __restrict__ v, f8& x) {
#pragma unroll
    for (int i = 0; i < 8; ++i) {
        float vi = v[i] * 0.5f + x.v[i];
        float sp = (vi >= 1.0f) ? 1.0f : 0.0f;
        v[i] = vi - sp;
        x.v[i] = sp;                 // spike overwrites the input slot
    }
}

__global__ __launch_bounds__(256) void lif_kernel(
    const float* __restrict__ x,
    float* __restrict__ out)
{
    const int tid = blockIdx.x * blockDim.x + threadIdx.x;  // 0 .. N_BATCH*SV8-1
    const int n  = tid >> 14;           // tid / SV8
    const int g  = tid & (SV8 - 1);     // tid % SV8

    const float* xp = x   + ((size_t)n * T_STEPS * SV8 + g) * 8;
    float*       op = out + ((size_t)n * T_STEPS * SV8 + g) * 8;
    const size_t stride = (size_t)SV8 * 8;   // one timestep plane, in floats

    float v[8];
#pragma unroll
    for (int i = 0; i < 8; ++i) v[i] = 0.0f;   // v_init == 0

#pragma unroll
    for (int tb = 0; tb < T_STEPS; tb += 4) {
        // 4 back-to-back LDG.256 (MLP=4, 128B/thread in flight)
        f8 x0 = ldg256(xp + (size_t)(tb + 0) * stride);
        f8 x1 = ldg256(xp + (size_t)(tb + 1) * stride);
        f8 x2 = ldg256(xp + (size_t)(tb + 2) * stride);
        f8 x3 = ldg256(xp + (size_t)(tb + 3) * stride);

        lif_step8(v, x0);
        lif_step8(v, x1);
        lif_step8(v, x2);
        lif_step8(v, x3);

        stg256(op + (size_t)(tb + 0) * stride, x0);
        stg256(op + (size_t)(tb + 1) * stride, x1);
        stg256(op + (size_t)(tb + 2) * stride, x2);
        stg256(op + (size_t)(tb + 3) * stride, x3);
    }
}

extern "C" void kernel_launch(void* const* d_in, const int* in_sizes, int n_in,
                              void* d_out, int out_size)
{
    const float* x   = (const float*)d_in[0];
    float*       out = (float*)d_out;

    const int total_threads = N_BATCH * SV8;   // 524,288
    const int block = 256;
    const int grid  = total_threads / block;   // 2048

    lif_kernel<<<grid, block>>>(x, out);
}